// round 16
// baseline (speedup 1.0000x reference)
#include <cuda_runtime.h>
#include <cuda_fp16.h>
#include <stdint.h>
#include <math.h>

// ---------------- problem constants ----------------
#define DD 1024
#define EE 8
#define MM 4096
#define GG 8
#define CAP 256
#define NTOK 8192
#define ROWS_E 2048
#define SLOTS 16384

// GEMM tiling: CTA 128x128, 8 warps of 64x32, BK=64, 3 stages, SW128 (R10)
#define BM 128
#define BN 128
#define BK 64
#define STAGES 3
#define STAGE_B 32768
#define SMEM_GEMM (STAGES * STAGE_B)   // 98304

#define SWZ128(o) ((o) ^ (((o) >> 3) & 0x70))

// ---------------- device scratch (static, allocation-free) ----------------
__device__ __align__(1024) float g_gates[NTOK * EE];
__device__ __align__(1024) int   g_tok_e[NTOK * 2];
__device__ __align__(1024) float g_tok_g[NTOK * 2];
__device__ __align__(1024) int   g_tok_slot[NTOK * 2];
__device__ __align__(1024) int   g_slot_token[SLOTS];
__device__ __align__(1024) float g_cv2[GG];
__device__ __align__(1024) __half g_xe[(size_t)SLOTS * DD];
__device__ __align__(1024) __half g_w1t[(size_t)EE * MM * DD];    // [E][M][D]
__device__ __align__(1024) __half g_w2t[(size_t)EE * DD * MM];    // [E][D][M]
__device__ __align__(1024) __half g_h[(size_t)SLOTS * MM];
__device__ __align__(1024) __half g_yeh[(size_t)SLOTS * DD];      // fp16 ye

// ---------------- PTX helpers (baseline PTX only) ----------------
__device__ __forceinline__ uint32_t smem_u32(const void* p) {
    uint32_t a;
    asm("{ .reg .u64 t; cvta.to.shared.u64 t, %1; cvt.u32.u64 %0, t; }"
        : "=r"(a) : "l"(p));
    return a;
}
#define CP16(dst, src) \
    asm volatile("cp.async.cg.shared.global [%0], [%1], 16;\n" :: "r"(dst), "l"(src))
#define CP_COMMIT() asm volatile("cp.async.commit_group;\n" ::: "memory")
#define CP_WAIT1()  asm volatile("cp.async.wait_group 1;\n" ::: "memory")
#define CP_WAIT0()  asm volatile("cp.async.wait_group 0;\n" ::: "memory")

__device__ __forceinline__ void ldsm4(uint32_t* r, uint32_t addr) {
    asm volatile("ldmatrix.sync.aligned.m8n8.x4.shared.b16 {%0,%1,%2,%3}, [%4];"
                 : "=r"(r[0]), "=r"(r[1]), "=r"(r[2]), "=r"(r[3]) : "r"(addr));
}
__device__ __forceinline__ void mma16816(float* d, const uint32_t* a,
                                         uint32_t b0, uint32_t b1) {
    asm volatile(
        "mma.sync.aligned.m16n8k16.row.col.f32.f16.f16.f32 "
        "{%0,%1,%2,%3}, {%4,%5,%6,%7}, {%8,%9}, {%0,%1,%2,%3};"
        : "+f"(d[0]), "+f"(d[1]), "+f"(d[2]), "+f"(d[3])
        : "r"(a[0]), "r"(a[1]), "r"(a[2]), "r"(a[3]), "r"(b0), "r"(b1));
}

// ---------------- router ----------------
__global__ void router_kernel(const float* __restrict__ x,
                              const float* __restrict__ wr) {
    int gwarp = (blockIdx.x * blockDim.x + threadIdx.x) >> 5;
    int lane = threadIdx.x & 31;
    if (gwarp >= NTOK) return;
    const float* xr = x + (size_t)gwarp * DD;
    float acc[EE];
#pragma unroll
    for (int e = 0; e < EE; e++) acc[e] = 0.f;
    for (int d = lane; d < DD; d += 32) {
        float xv = __ldg(xr + d);
        const float4* w4 = (const float4*)(wr + (size_t)d * EE);
        float4 w0 = __ldg(w4);
        float4 w1 = __ldg(w4 + 1);
        acc[0] = fmaf(xv, w0.x, acc[0]); acc[1] = fmaf(xv, w0.y, acc[1]);
        acc[2] = fmaf(xv, w0.z, acc[2]); acc[3] = fmaf(xv, w0.w, acc[3]);
        acc[4] = fmaf(xv, w1.x, acc[4]); acc[5] = fmaf(xv, w1.y, acc[5]);
        acc[6] = fmaf(xv, w1.z, acc[6]); acc[7] = fmaf(xv, w1.w, acc[7]);
    }
#pragma unroll
    for (int off = 16; off > 0; off >>= 1)
#pragma unroll
        for (int e = 0; e < EE; e++)
            acc[e] += __shfl_down_sync(0xffffffffu, acc[e], off);
    if (lane == 0) {
        float mx = acc[0];
#pragma unroll
        for (int e = 1; e < EE; e++) mx = fmaxf(mx, acc[e]);
        float gv[EE], s = 0.f;
#pragma unroll
        for (int e = 0; e < EE; e++) { gv[e] = expf(acc[e] - mx); s += gv[e]; }
        float inv = 1.f / s;
#pragma unroll
        for (int e = 0; e < EE; e++) { gv[e] *= inv; g_gates[gwarp * EE + e] = gv[e]; }
        int i0 = 0;
#pragma unroll
        for (int e = 1; e < EE; e++) if (acc[e] > acc[i0]) i0 = e;
        int i1 = (i0 == 0) ? 1 : 0;
#pragma unroll
        for (int e = 0; e < EE; e++) if (e != i0 && acc[e] > acc[i1]) i1 = e;
        g_tok_e[gwarp * 2 + 0] = i0;
        g_tok_e[gwarp * 2 + 1] = i1;
        g_tok_g[gwarp * 2 + 0] = gv[i0];
        g_tok_g[gwarp * 2 + 1] = gv[i1];
    }
}

// ---------------- importance / aux loss ----------------
__global__ void imp_kernel() {
    int g = blockIdx.x;
    int tid = threadIdx.x;
    float acc[EE];
#pragma unroll
    for (int e = 0; e < EE; e++) acc[e] = 0.f;
    for (int t = tid; t < 1024; t += 256) {
        const float* gp = g_gates + (size_t)(g * 1024 + t) * EE;
#pragma unroll
        for (int e = 0; e < EE; e++) acc[e] += gp[e];
    }
    __shared__ float sh[EE][256];
#pragma unroll
    for (int e = 0; e < EE; e++) sh[e][tid] = acc[e];
    __syncthreads();
    for (int off = 128; off > 0; off >>= 1) {
        if (tid < off)
#pragma unroll
            for (int e = 0; e < EE; e++) sh[e][tid] += sh[e][tid + off];
        __syncthreads();
    }
    if (tid == 0) {
        float mean = 0.f;
#pragma unroll
        for (int e = 0; e < EE; e++) mean += sh[e][0];
        mean *= (1.f / EE);
        float var = 0.f;
#pragma unroll
        for (int e = 0; e < EE; e++) { float d = sh[e][0] - mean; var += d * d; }
        var *= (1.f / EE);
        g_cv2[g] = var / (mean * mean);
    }
}

__global__ void aux_kernel(float* __restrict__ out) {
    float s = 0.f;
#pragma unroll
    for (int g = 0; g < GG; g++) s += g_cv2[g];
    out[(size_t)NTOK * DD] = s * (1.f / GG);
}

// ---------------- ballot-based deterministic capacity scan ----------------
__global__ void scan_kernel() {
    int g = blockIdx.x;
    int t = threadIdx.x;          // 1024
    int w = t >> 5, lane = t & 31;
    int tg = g * 1024 + t;
    int e0 = g_tok_e[tg * 2 + 0];
    int e1 = g_tok_e[tg * 2 + 1];
    __shared__ int warpcnt[32][8];
    __shared__ int warpbase[32][8];
    __shared__ int tot0[8];
    __shared__ int filled[8];
    unsigned lt = (1u << lane) - 1u;
    unsigned m[8];

#pragma unroll
    for (int e = 0; e < 8; e++) m[e] = __ballot_sync(0xffffffffu, e0 == e);
    if (lane < 8) warpcnt[w][lane] = __popc(m[lane]);
    int intra0 = __popc(m[e0] & lt);
    __syncthreads();
    if (t < 256) {
        int e = t >> 5, wi = lane;
        int val = warpcnt[wi][e];
        int incl = val;
#pragma unroll
        for (int off = 1; off < 32; off <<= 1) {
            int n = __shfl_up_sync(0xffffffffu, incl, off);
            if (wi >= off) incl += n;
        }
        warpbase[wi][e] = incl - val;
        if (wi == 31) tot0[e] = incl;
    }
    __syncthreads();
    int pos0 = warpbase[w][e0] + intra0;
    __syncthreads();

#pragma unroll
    for (int e = 0; e < 8; e++) m[e] = __ballot_sync(0xffffffffu, e1 == e);
    if (lane < 8) warpcnt[w][lane] = __popc(m[lane]);
    int intra1 = __popc(m[e1] & lt);
    __syncthreads();
    if (t < 256) {
        int e = t >> 5, wi = lane;
        int val = warpcnt[wi][e];
        int incl = val;
#pragma unroll
        for (int off = 1; off < 32; off <<= 1) {
            int n = __shfl_up_sync(0xffffffffu, incl, off);
            if (wi >= off) incl += n;
        }
        warpbase[wi][e] = incl - val;
        if (wi == 31) filled[e] = min(tot0[e] + incl, CAP);
    }
    __syncthreads();
    int pos1 = tot0[e1] + warpbase[w][e1] + intra1;

    int slot0 = (pos0 < CAP) ? pos0 : -1;
    int slot1 = (pos1 < CAP) ? pos1 : -1;
    g_tok_slot[tg * 2 + 0] = slot0;
    g_tok_slot[tg * 2 + 1] = slot1;
    if (slot0 >= 0) g_slot_token[(e0 * GG + g) * CAP + slot0] = tg;
    if (slot1 >= 0) g_slot_token[(e1 * GG + g) * CAP + slot1] = tg;
    __syncthreads();
    for (int idx = t; idx < EE * CAP; idx += 1024) {
        int e = idx / CAP, c = idx % CAP;
        if (c >= filled[e]) g_slot_token[(e * GG + g) * CAP + c] = -1;
    }
}

// ---------------- gather tokens -> fp16 expert buffers ----------------
__global__ void gather_kernel(const float* __restrict__ x) {
    int s_id = blockIdx.x;
    int tok = g_slot_token[s_id];
    int t = threadIdx.x;  // 128
    __half* dst = g_xe + (size_t)s_id * DD;
    if (tok >= 0) {
        const float4* src = (const float4*)(x + (size_t)tok * DD);
        float4 a = src[2 * t], b = src[2 * t + 1];
        __half h8[8];
        h8[0] = __float2half(a.x); h8[1] = __float2half(a.y);
        h8[2] = __float2half(a.z); h8[3] = __float2half(a.w);
        h8[4] = __float2half(b.x); h8[5] = __float2half(b.y);
        h8[6] = __float2half(b.z); h8[7] = __float2half(b.w);
        ((uint4*)dst)[t] = *(uint4*)h8;
    } else {
        ((uint4*)dst)[t] = make_uint4(0, 0, 0, 0);
    }
}

// -------- weight transpose + fp16 convert: in[e][R][C] -> out[e][C][R] -----
template <int R, int C>
__global__ void transpose_half_kernel(const float* __restrict__ in,
                                      __half* __restrict__ out) {
    __shared__ float tile[32][66];
    int e = blockIdx.z;
    int rb = blockIdx.y * 64, cb = blockIdx.x * 32;
    const float* ip = in + (size_t)e * R * C;
    __half* op = out + (size_t)e * C * R;
    int tx = threadIdx.x, ty = threadIdx.y;  // 32 x 8
#pragma unroll
    for (int j = 0; j < 8; j++) {
        int r = ty + j * 8;
        tile[tx][r] = ip[(size_t)(rb + r) * C + cb + tx];
    }
    __syncthreads();
#pragma unroll
    for (int j = 0; j < 4; j++) {
        int oc = ty + j * 8;
        float2 v = *(const float2*)&tile[oc][2 * tx];
        *(__half2*)&op[(size_t)(cb + oc) * R + rb + 2 * tx] =
            __floats2half2_rn(v.x, v.y);
    }
}

// ---------------- fast tanh-gelu ----------------
__device__ __forceinline__ float gelu_f(float v) {
    float u = 0.7978845608028654f * (v + 0.044715f * v * v * v);
    float ex = __expf(2.f * u);
    float th = 1.f - 2.f / (ex + 1.f);
    return 0.5f * v * (1.f + th);
}

// ------------- stage loader: A 128x64 + B 128x64 fp16, SW128 swizzle -------
__device__ __forceinline__ void load_stage(uint32_t st,
                                           const __half* __restrict__ Ae,
                                           const __half* __restrict__ Be,
                                           int kc, int K, int tid) {
#pragma unroll
    for (int j = 0; j < 4; j++) {
        int v = tid + j * 256;
        int row = v >> 3, c = v & 7;
        uint32_t off = SWZ128((uint32_t)(row * 128 + c * 16));
        CP16(st + off, Ae + (size_t)row * K + kc + c * 8);
    }
#pragma unroll
    for (int j = 0; j < 4; j++) {
        int v = tid + j * 256;
        int row = v >> 3, c = v & 7;
        uint32_t off = SWZ128((uint32_t)(row * 128 + c * 16));
        CP16(st + 16384u + off, Be + (size_t)row * K + kc + c * 8);
    }
}

// ---------------- HMMA GEMM (R10 mainloop, unified fp16 epilogue) ---------
// e = blockIdx.z + eoff (supports per-expert-chunk launches).
template <int K_DIM, bool GELU>
__global__ void __launch_bounds__(256, 2)
hmma_gemm_kernel(const __half* __restrict__ A, const __half* __restrict__ B,
                 const float* __restrict__ bias, __half* __restrict__ Cout,
                 int Ntot, int eoff) {
    constexpr int NC = K_DIM / BK;
    extern __shared__ char smem[];
    __shared__ float bs[BN];
    const uint32_t sb = smem_u32(smem);
    const int tid = threadIdx.x;
    const int lane = tid & 31;
    const int wid = tid >> 5;
    const int wm = wid & 1;
    const int wn = wid >> 1;
    const int e = blockIdx.z + eoff;
    const int m0 = blockIdx.y * BM;
    const int n0 = blockIdx.x * BN;

    const __half* Ae = A + ((size_t)(e * ROWS_E + m0)) * K_DIM;
    const __half* Be = B + ((size_t)e * Ntot + n0) * K_DIM;

    if (tid < BN) bs[tid] = __ldg(bias + (size_t)e * Ntot + n0 + tid);

    const int l15 = lane & 15;
    const int l16 = lane >> 4;
    uint32_t aAddr[4], bAddr[2];
#pragma unroll
    for (int mi = 0; mi < 4; mi++)
        aAddr[mi] = sb + SWZ128((uint32_t)((wm * 64 + mi * 16 + l15) * 128 + l16 * 16));
#pragma unroll
    for (int ni = 0; ni < 2; ni++)
        bAddr[ni] = sb + 16384u +
                    SWZ128((uint32_t)((wn * 32 + ni * 16 + l15) * 128 + l16 * 16));

    float acc[4][4][4];
#pragma unroll
    for (int i = 0; i < 4; i++)
#pragma unroll
        for (int j = 0; j < 4; j++)
#pragma unroll
            for (int k = 0; k < 4; k++) acc[i][j][k] = 0.f;

    // prologue: 2 stages
    load_stage(sb, Ae, Be, 0, K_DIM, tid);
    CP_COMMIT();
    load_stage(sb + STAGE_B, Ae, Be, BK, K_DIM, tid);
    CP_COMMIT();

#pragma unroll 1
    for (int i = 0; i < NC; i++) {
        CP_WAIT1();
        __syncthreads();
        {
            int nx = i + 2;
            if (nx < NC) {
                int sx = nx % STAGES;
                load_stage(sb + (uint32_t)sx * STAGE_B, Ae, Be, nx * BK, K_DIM, tid);
            }
        }
        CP_COMMIT();

        const uint32_t so = (uint32_t)(i % STAGES) * STAGE_B;
#pragma unroll
        for (int ks = 0; ks < 4; ks++) {
            const uint32_t xv = (uint32_t)ks * 32u;
            uint32_t a[4][4], bb[2][4];
#pragma unroll
            for (int mi = 0; mi < 4; mi++) ldsm4(a[mi], (aAddr[mi] + so) ^ xv);
#pragma unroll
            for (int ni = 0; ni < 2; ni++) ldsm4(bb[ni], (bAddr[ni] + so) ^ xv);
#pragma unroll
            for (int mi = 0; mi < 4; mi++) {
#pragma unroll
                for (int f = 0; f < 4; f++) {
                    int ni = f >> 1, ss = f & 1;
                    mma16816(acc[mi][f], a[mi], bb[ni][ss], bb[ni][ss + 2]);
                }
            }
        }
    }
    CP_WAIT0();
    __syncthreads();

    // ---------------- unified fp16 smem-staged epilogue ----------------
    const int rbase = wm * 64 + (lane >> 2);
    __half* sC = (__half*)smem;          // [128][136] halfs (272B stride)
#pragma unroll
    for (int mi = 0; mi < 4; mi++) {
#pragma unroll
        for (int f = 0; f < 4; f++) {
            int cidx = wn * 32 + (f >> 1) * 16 + (f & 1) * 8 + (lane & 3) * 2;
            float b0v = bs[cidx], b1v = bs[cidx + 1];
            int r0 = rbase + mi * 16;
            float v0 = acc[mi][f][0] + b0v, v1 = acc[mi][f][1] + b1v;
            float v2 = acc[mi][f][2] + b0v, v3 = acc[mi][f][3] + b1v;
            if (GELU) {
                v0 = gelu_f(v0); v1 = gelu_f(v1);
                v2 = gelu_f(v2); v3 = gelu_f(v3);
            }
            *(__half2*)&sC[r0 * 136 + cidx] = __floats2half2_rn(v0, v1);
            *(__half2*)&sC[(r0 + 8) * 136 + cidx] = __floats2half2_rn(v2, v3);
        }
    }
    __syncthreads();
    // 128 rows x 16 segments x 8 halfs (16B) = 128 cols per row
    for (int v = tid; v < 128 * 16; v += 256) {
        int row = v >> 4, seg = v & 15;
        *(uint4*)(Cout + (size_t)(e * ROWS_E + m0 + row) * Ntot + n0 + seg * 8) =
            *(const uint4*)&sC[row * 136 + seg * 8];
    }
}

// ---------------- weighted combine (fp16 ye) ----------------
__global__ void combine_kernel(float* __restrict__ out) {
    int tg = blockIdx.x;
    int g = tg >> 10;
    float4 acc = make_float4(0.f, 0.f, 0.f, 0.f);
#pragma unroll
    for (int k = 0; k < 2; k++) {
        int slot = g_tok_slot[tg * 2 + k];
        if (slot >= 0) {
            int e = g_tok_e[tg * 2 + k];
            float gv = g_tok_g[tg * 2 + k];
            const __half2* row =
                (const __half2*)(g_yeh + ((size_t)(e * GG + g) * CAP + slot) * DD);
            __half2 h0 = row[2 * threadIdx.x];
            __half2 h1 = row[2 * threadIdx.x + 1];
            float2 f0 = __half22float2(h0);
            float2 f1 = __half22float2(h1);
            acc.x = fmaf(gv, f0.x, acc.x);
            acc.y = fmaf(gv, f0.y, acc.y);
            acc.z = fmaf(gv, f1.x, acc.z);
            acc.w = fmaf(gv, f1.y, acc.w);
        }
    }
    ((float4*)(out + (size_t)tg * DD))[threadIdx.x] = acc;
}

// ---------------- launch ----------------
extern "C" void kernel_launch(void* const* d_in, const int* in_sizes, int n_in,
                              void* d_out, int out_size) {
    const float* x  = (const float*)d_in[0];
    const float* wr = (const float*)d_in[1];
    const float* w1 = (const float*)d_in[2];
    const float* b1 = (const float*)d_in[3];
    const float* w2 = (const float*)d_in[4];
    const float* b2 = (const float*)d_in[5];
    float* out = (float*)d_out;

    __half *xe, *w1t, *w2t, *h, *yeh;
    cudaGetSymbolAddress((void**)&xe, g_xe);
    cudaGetSymbolAddress((void**)&w1t, g_w1t);
    cudaGetSymbolAddress((void**)&w2t, g_w2t);
    cudaGetSymbolAddress((void**)&h, g_h);
    cudaGetSymbolAddress((void**)&yeh, g_yeh);

    cudaFuncSetAttribute(hmma_gemm_kernel<1024, true>,
                         cudaFuncAttributeMaxDynamicSharedMemorySize, SMEM_GEMM);
    cudaFuncSetAttribute(hmma_gemm_kernel<4096, false>,
                         cudaFuncAttributeMaxDynamicSharedMemorySize, SMEM_GEMM);

    // Streams/events created once on the first (uncaptured) correctness call
    // and reused; identical GPU work per call (graph-capture safe fork-join).
    static cudaStream_t s1 = nullptr;
    static cudaEvent_t evFork = nullptr, evW1a = nullptr, evW1b = nullptr;
    static cudaEvent_t evW2 = nullptr, evR = nullptr, evAux = nullptr;
    if (s1 == nullptr) {
        cudaStreamCreateWithFlags(&s1, cudaStreamNonBlocking);
        cudaEventCreateWithFlags(&evFork, cudaEventDisableTiming);
        cudaEventCreateWithFlags(&evW1a, cudaEventDisableTiming);
        cudaEventCreateWithFlags(&evW1b, cudaEventDisableTiming);
        cudaEventCreateWithFlags(&evW2, cudaEventDisableTiming);
        cudaEventCreateWithFlags(&evR, cudaEventDisableTiming);
        cudaEventCreateWithFlags(&evAux, cudaEventDisableTiming);
    }

    // Fork: transposes + (imp,aux) on s1 concurrent with routing/GEMM chain.
    cudaEventRecord(evFork, 0);
    cudaStreamWaitEvent(s1, evFork, 0);

    // s1: w1 transpose in two expert chunks (0-3, 4-7), then w2 transpose
    transpose_half_kernel<1024, 4096>
        <<<dim3(4096 / 32, 1024 / 64, 4), dim3(32, 8), 0, s1>>>(w1, w1t);
    cudaEventRecord(evW1a, s1);
    transpose_half_kernel<1024, 4096>
        <<<dim3(4096 / 32, 1024 / 64, 4), dim3(32, 8), 0, s1>>>(
            w1 + (size_t)4 * 1024 * 4096, w1t + (size_t)4 * 4096 * 1024);
    cudaEventRecord(evW1b, s1);
    transpose_half_kernel<4096, 1024>
        <<<dim3(1024 / 32, 4096 / 64, EE), dim3(32, 8), 0, s1>>>(w2, w2t);
    cudaEventRecord(evW2, s1);

    // stream 0: routing chain
    router_kernel<<<NTOK / 8, 256>>>(x, wr);
    cudaEventRecord(evR, 0);
    scan_kernel<<<GG, 1024>>>();
    gather_kernel<<<SLOTS, 128>>>(x);

    // s1: aux-loss chain (depends only on router output)
    cudaStreamWaitEvent(s1, evR, 0);
    imp_kernel<<<GG, 256, 0, s1>>>();
    if (out_size > NTOK * DD) aux_kernel<<<1, 1, 0, s1>>>(out);
    cudaEventRecord(evAux, s1);

    // GEMM1 in two 4-expert chunks, each gated on its transpose chunk
    cudaStreamWaitEvent(0, evW1a, 0);
    hmma_gemm_kernel<1024, true>
        <<<dim3(MM / BN, ROWS_E / BM, 4), 256, SMEM_GEMM>>>(
            xe, w1t, b1, h, MM, 0);
    cudaStreamWaitEvent(0, evW1b, 0);
    hmma_gemm_kernel<1024, true>
        <<<dim3(MM / BN, ROWS_E / BM, 4), 256, SMEM_GEMM>>>(
            xe, w1t, b1, h, MM, 4);

    // GEMM2 (all experts) gated on w2 transpose
    cudaStreamWaitEvent(0, evW2, 0);
    hmma_gemm_kernel<4096, false>
        <<<dim3(DD / BN, ROWS_E / BM, EE), 256, SMEM_GEMM>>>(
            h, w2t, b2, yeh, DD, 0);

    // Join aux chain back into stream 0 before the final kernel.
    cudaStreamWaitEvent(0, evAux, 0);
    combine_kernel<<<NTOK, 256>>>(out);
}

// round 17
// speedup vs baseline: 1.0055x; 1.0055x over previous
#include <cuda_runtime.h>
#include <cuda_fp16.h>
#include <stdint.h>
#include <math.h>

// ---------------- problem constants ----------------
#define DD 1024
#define EE 8
#define MM 4096
#define GG 8
#define CAP 256
#define NTOK 8192
#define ROWS_E 2048
#define SLOTS 16384

// GEMM tiling: CTA 128x128, 8 warps of 64x32, BK=64, 3 stages, SW128 (R10)
#define BM 128
#define BN 128
#define BK 64
#define STAGES 3
#define STAGE_B 32768
#define SMEM_GEMM (STAGES * STAGE_B)   // 98304

#define SWZ128(o) ((o) ^ (((o) >> 3) & 0x70))

// ---------------- device scratch (static, allocation-free) ----------------
__device__ __align__(1024) float g_gates[NTOK * EE];
__device__ __align__(1024) int   g_tok_e[NTOK * 2];
__device__ __align__(1024) float g_tok_g[NTOK * 2];
__device__ __align__(1024) int   g_tok_slot[NTOK * 2];
__device__ __align__(1024) int   g_slot_token[SLOTS];
__device__ __align__(1024) float g_cv2[GG];
__device__ __align__(1024) __half g_xe[(size_t)SLOTS * DD];
__device__ __align__(1024) __half g_w1t[(size_t)EE * MM * DD];    // [E][M][D]
__device__ __align__(1024) __half g_w2t[(size_t)EE * DD * MM];    // [E][D][M]
__device__ __align__(1024) __half g_h[(size_t)SLOTS * MM];

// ---------------- PTX helpers (baseline PTX only) ----------------
__device__ __forceinline__ uint32_t smem_u32(const void* p) {
    uint32_t a;
    asm("{ .reg .u64 t; cvta.to.shared.u64 t, %1; cvt.u32.u64 %0, t; }"
        : "=r"(a) : "l"(p));
    return a;
}
#define CP16(dst, src) \
    asm volatile("cp.async.cg.shared.global [%0], [%1], 16;\n" :: "r"(dst), "l"(src))
#define CP_COMMIT() asm volatile("cp.async.commit_group;\n" ::: "memory")
#define CP_WAIT1()  asm volatile("cp.async.wait_group 1;\n" ::: "memory")
#define CP_WAIT0()  asm volatile("cp.async.wait_group 0;\n" ::: "memory")

__device__ __forceinline__ void ldsm4(uint32_t* r, uint32_t addr) {
    asm volatile("ldmatrix.sync.aligned.m8n8.x4.shared.b16 {%0,%1,%2,%3}, [%4];"
                 : "=r"(r[0]), "=r"(r[1]), "=r"(r[2]), "=r"(r[3]) : "r"(addr));
}
__device__ __forceinline__ void mma16816(float* d, const uint32_t* a,
                                         uint32_t b0, uint32_t b1) {
    asm volatile(
        "mma.sync.aligned.m16n8k16.row.col.f32.f16.f16.f32 "
        "{%0,%1,%2,%3}, {%4,%5,%6,%7}, {%8,%9}, {%0,%1,%2,%3};"
        : "+f"(d[0]), "+f"(d[1]), "+f"(d[2]), "+f"(d[3])
        : "r"(a[0]), "r"(a[1]), "r"(a[2]), "r"(a[3]), "r"(b0), "r"(b1));
}

// ---------------- router ----------------
__global__ void router_kernel(const float* __restrict__ x,
                              const float* __restrict__ wr) {
    int gwarp = (blockIdx.x * blockDim.x + threadIdx.x) >> 5;
    int lane = threadIdx.x & 31;
    if (gwarp >= NTOK) return;
    const float* xr = x + (size_t)gwarp * DD;
    float acc[EE];
#pragma unroll
    for (int e = 0; e < EE; e++) acc[e] = 0.f;
    for (int d = lane; d < DD; d += 32) {
        float xv = __ldg(xr + d);
        const float4* w4 = (const float4*)(wr + (size_t)d * EE);
        float4 w0 = __ldg(w4);
        float4 w1 = __ldg(w4 + 1);
        acc[0] = fmaf(xv, w0.x, acc[0]); acc[1] = fmaf(xv, w0.y, acc[1]);
        acc[2] = fmaf(xv, w0.z, acc[2]); acc[3] = fmaf(xv, w0.w, acc[3]);
        acc[4] = fmaf(xv, w1.x, acc[4]); acc[5] = fmaf(xv, w1.y, acc[5]);
        acc[6] = fmaf(xv, w1.z, acc[6]); acc[7] = fmaf(xv, w1.w, acc[7]);
    }
#pragma unroll
    for (int off = 16; off > 0; off >>= 1)
#pragma unroll
        for (int e = 0; e < EE; e++)
            acc[e] += __shfl_down_sync(0xffffffffu, acc[e], off);
    if (lane == 0) {
        float mx = acc[0];
#pragma unroll
        for (int e = 1; e < EE; e++) mx = fmaxf(mx, acc[e]);
        float gv[EE], s = 0.f;
#pragma unroll
        for (int e = 0; e < EE; e++) { gv[e] = expf(acc[e] - mx); s += gv[e]; }
        float inv = 1.f / s;
#pragma unroll
        for (int e = 0; e < EE; e++) { gv[e] *= inv; g_gates[gwarp * EE + e] = gv[e]; }
        int i0 = 0;
#pragma unroll
        for (int e = 1; e < EE; e++) if (acc[e] > acc[i0]) i0 = e;
        int i1 = (i0 == 0) ? 1 : 0;
#pragma unroll
        for (int e = 0; e < EE; e++) if (e != i0 && acc[e] > acc[i1]) i1 = e;
        g_tok_e[gwarp * 2 + 0] = i0;
        g_tok_e[gwarp * 2 + 1] = i1;
        g_tok_g[gwarp * 2 + 0] = gv[i0];
        g_tok_g[gwarp * 2 + 1] = gv[i1];
    }
}

// ---------------- importance / aux loss ----------------
__global__ void imp_kernel() {
    int g = blockIdx.x;
    int tid = threadIdx.x;
    float acc[EE];
#pragma unroll
    for (int e = 0; e < EE; e++) acc[e] = 0.f;
    for (int t = tid; t < 1024; t += 256) {
        const float* gp = g_gates + (size_t)(g * 1024 + t) * EE;
#pragma unroll
        for (int e = 0; e < EE; e++) acc[e] += gp[e];
    }
    __shared__ float sh[EE][256];
#pragma unroll
    for (int e = 0; e < EE; e++) sh[e][tid] = acc[e];
    __syncthreads();
    for (int off = 128; off > 0; off >>= 1) {
        if (tid < off)
#pragma unroll
            for (int e = 0; e < EE; e++) sh[e][tid] += sh[e][tid + off];
        __syncthreads();
    }
    if (tid == 0) {
        float mean = 0.f;
#pragma unroll
        for (int e = 0; e < EE; e++) mean += sh[e][0];
        mean *= (1.f / EE);
        float var = 0.f;
#pragma unroll
        for (int e = 0; e < EE; e++) { float d = sh[e][0] - mean; var += d * d; }
        var *= (1.f / EE);
        g_cv2[g] = var / (mean * mean);
    }
}

__global__ void aux_kernel(float* __restrict__ out) {
    float s = 0.f;
#pragma unroll
    for (int g = 0; g < GG; g++) s += g_cv2[g];
    out[(size_t)NTOK * DD] = s * (1.f / GG);
}

// ---------------- zero the token-output region ----------------
__global__ void zero_out_kernel(float* __restrict__ out) {
    ((float4*)out)[(size_t)blockIdx.x * 256 + threadIdx.x] =
        make_float4(0.f, 0.f, 0.f, 0.f);
}

// ---------------- ballot-based deterministic capacity scan ----------------
__global__ void scan_kernel() {
    int g = blockIdx.x;
    int t = threadIdx.x;          // 1024
    int w = t >> 5, lane = t & 31;
    int tg = g * 1024 + t;
    int e0 = g_tok_e[tg * 2 + 0];
    int e1 = g_tok_e[tg * 2 + 1];
    __shared__ int warpcnt[32][8];
    __shared__ int warpbase[32][8];
    __shared__ int tot0[8];
    __shared__ int filled[8];
    unsigned lt = (1u << lane) - 1u;
    unsigned m[8];

#pragma unroll
    for (int e = 0; e < 8; e++) m[e] = __ballot_sync(0xffffffffu, e0 == e);
    if (lane < 8) warpcnt[w][lane] = __popc(m[lane]);
    int intra0 = __popc(m[e0] & lt);
    __syncthreads();
    if (t < 256) {
        int e = t >> 5, wi = lane;
        int val = warpcnt[wi][e];
        int incl = val;
#pragma unroll
        for (int off = 1; off < 32; off <<= 1) {
            int n = __shfl_up_sync(0xffffffffu, incl, off);
            if (wi >= off) incl += n;
        }
        warpbase[wi][e] = incl - val;
        if (wi == 31) tot0[e] = incl;
    }
    __syncthreads();
    int pos0 = warpbase[w][e0] + intra0;
    __syncthreads();

#pragma unroll
    for (int e = 0; e < 8; e++) m[e] = __ballot_sync(0xffffffffu, e1 == e);
    if (lane < 8) warpcnt[w][lane] = __popc(m[lane]);
    int intra1 = __popc(m[e1] & lt);
    __syncthreads();
    if (t < 256) {
        int e = t >> 5, wi = lane;
        int val = warpcnt[wi][e];
        int incl = val;
#pragma unroll
        for (int off = 1; off < 32; off <<= 1) {
            int n = __shfl_up_sync(0xffffffffu, incl, off);
            if (wi >= off) incl += n;
        }
        warpbase[wi][e] = incl - val;
        if (wi == 31) filled[e] = min(tot0[e] + incl, CAP);
    }
    __syncthreads();
    int pos1 = tot0[e1] + warpbase[w][e1] + intra1;

    int slot0 = (pos0 < CAP) ? pos0 : -1;
    int slot1 = (pos1 < CAP) ? pos1 : -1;
    g_tok_slot[tg * 2 + 0] = slot0;
    g_tok_slot[tg * 2 + 1] = slot1;
    if (slot0 >= 0) g_slot_token[(e0 * GG + g) * CAP + slot0] = tg;
    if (slot1 >= 0) g_slot_token[(e1 * GG + g) * CAP + slot1] = tg;
    __syncthreads();
    for (int idx = t; idx < EE * CAP; idx += 1024) {
        int e = idx / CAP, c = idx % CAP;
        if (c >= filled[e]) g_slot_token[(e * GG + g) * CAP + c] = -1;
    }
}

// ---------------- gather tokens -> fp16 expert buffers ----------------
__global__ void gather_kernel(const float* __restrict__ x) {
    int s_id = blockIdx.x;
    int tok = g_slot_token[s_id];
    int t = threadIdx.x;  // 128
    __half* dst = g_xe + (size_t)s_id * DD;
    if (tok >= 0) {
        const float4* src = (const float4*)(x + (size_t)tok * DD);
        float4 a = src[2 * t], b = src[2 * t + 1];
        __half h8[8];
        h8[0] = __float2half(a.x); h8[1] = __float2half(a.y);
        h8[2] = __float2half(a.z); h8[3] = __float2half(a.w);
        h8[4] = __float2half(b.x); h8[5] = __float2half(b.y);
        h8[6] = __float2half(b.z); h8[7] = __float2half(b.w);
        ((uint4*)dst)[t] = *(uint4*)h8;
    } else {
        ((uint4*)dst)[t] = make_uint4(0, 0, 0, 0);
    }
}

// -------- weight transpose + fp16 convert: in[e][R][C] -> out[e][C][R] -----
template <int R, int C>
__global__ void transpose_half_kernel(const float* __restrict__ in,
                                      __half* __restrict__ out) {
    __shared__ float tile[32][66];
    int e = blockIdx.z;
    int rb = blockIdx.y * 64, cb = blockIdx.x * 32;
    const float* ip = in + (size_t)e * R * C;
    __half* op = out + (size_t)e * C * R;
    int tx = threadIdx.x, ty = threadIdx.y;  // 32 x 8
#pragma unroll
    for (int j = 0; j < 8; j++) {
        int r = ty + j * 8;
        tile[tx][r] = ip[(size_t)(rb + r) * C + cb + tx];
    }
    __syncthreads();
#pragma unroll
    for (int j = 0; j < 4; j++) {
        int oc = ty + j * 8;
        float2 v = *(const float2*)&tile[oc][2 * tx];
        *(__half2*)&op[(size_t)(cb + oc) * R + rb + 2 * tx] =
            __floats2half2_rn(v.x, v.y);
    }
}

// ---------------- fast tanh-gelu ----------------
__device__ __forceinline__ float gelu_f(float v) {
    float u = 0.7978845608028654f * (v + 0.044715f * v * v * v);
    float ex = __expf(2.f * u);
    float th = 1.f - 2.f / (ex + 1.f);
    return 0.5f * v * (1.f + th);
}

// ------------- stage loader: A 128x64 + B 128x64 fp16, SW128 swizzle -------
__device__ __forceinline__ void load_stage(uint32_t st,
                                           const __half* __restrict__ Ae,
                                           const __half* __restrict__ Be,
                                           int kc, int K, int tid) {
#pragma unroll
    for (int j = 0; j < 4; j++) {
        int v = tid + j * 256;
        int row = v >> 3, c = v & 7;
        uint32_t off = SWZ128((uint32_t)(row * 128 + c * 16));
        CP16(st + off, Ae + (size_t)row * K + kc + c * 8);
    }
#pragma unroll
    for (int j = 0; j < 4; j++) {
        int v = tid + j * 256;
        int row = v >> 3, c = v & 7;
        uint32_t off = SWZ128((uint32_t)(row * 128 + c * 16));
        CP16(st + 16384u + off, Be + (size_t)row * K + kc + c * 8);
    }
}

// ---------------- HMMA GEMM (R10 mainloop) ----------------
// GELU=true:  C (fp16 h) = gelu(A*B^T + bias), smem-staged coalesced stores.
// GELU=false: fused combine — atomicAdd(gate * (A*B^T + bias)) into out[token]
//             per slot row (<=2 contributions per out element -> deterministic).
template <int K_DIM, bool GELU>
__global__ void __launch_bounds__(256, 2)
hmma_gemm_kernel(const __half* __restrict__ A, const __half* __restrict__ B,
                 const float* __restrict__ bias, __half* __restrict__ Ch,
                 float* __restrict__ fout, int Ntot) {
    constexpr int NC = K_DIM / BK;
    extern __shared__ char smem[];
    __shared__ float bs[BN];
    const uint32_t sb = smem_u32(smem);
    const int tid = threadIdx.x;
    const int lane = tid & 31;
    const int wid = tid >> 5;
    const int wm = wid & 1;
    const int wn = wid >> 1;
    const int e = blockIdx.z;
    const int m0 = blockIdx.y * BM;
    const int n0 = blockIdx.x * BN;

    const __half* Ae = A + ((size_t)(e * ROWS_E + m0)) * K_DIM;
    const __half* Be = B + ((size_t)e * Ntot + n0) * K_DIM;

    if (tid < BN) bs[tid] = __ldg(bias + (size_t)e * Ntot + n0 + tid);

    const int l15 = lane & 15;
    const int l16 = lane >> 4;
    uint32_t aAddr[4], bAddr[2];
#pragma unroll
    for (int mi = 0; mi < 4; mi++)
        aAddr[mi] = sb + SWZ128((uint32_t)((wm * 64 + mi * 16 + l15) * 128 + l16 * 16));
#pragma unroll
    for (int ni = 0; ni < 2; ni++)
        bAddr[ni] = sb + 16384u +
                    SWZ128((uint32_t)((wn * 32 + ni * 16 + l15) * 128 + l16 * 16));

    float acc[4][4][4];
#pragma unroll
    for (int i = 0; i < 4; i++)
#pragma unroll
        for (int j = 0; j < 4; j++)
#pragma unroll
            for (int k = 0; k < 4; k++) acc[i][j][k] = 0.f;

    // prologue: 2 stages
    load_stage(sb, Ae, Be, 0, K_DIM, tid);
    CP_COMMIT();
    load_stage(sb + STAGE_B, Ae, Be, BK, K_DIM, tid);
    CP_COMMIT();

#pragma unroll 1
    for (int i = 0; i < NC; i++) {
        CP_WAIT1();
        __syncthreads();
        {
            int nx = i + 2;
            if (nx < NC) {
                int sx = nx % STAGES;
                load_stage(sb + (uint32_t)sx * STAGE_B, Ae, Be, nx * BK, K_DIM, tid);
            }
        }
        CP_COMMIT();

        const uint32_t so = (uint32_t)(i % STAGES) * STAGE_B;
#pragma unroll
        for (int ks = 0; ks < 4; ks++) {
            const uint32_t xv = (uint32_t)ks * 32u;
            uint32_t a[4][4], bb[2][4];
#pragma unroll
            for (int mi = 0; mi < 4; mi++) ldsm4(a[mi], (aAddr[mi] + so) ^ xv);
#pragma unroll
            for (int ni = 0; ni < 2; ni++) ldsm4(bb[ni], (bAddr[ni] + so) ^ xv);
#pragma unroll
            for (int mi = 0; mi < 4; mi++) {
#pragma unroll
                for (int f = 0; f < 4; f++) {
                    int ni = f >> 1, ss = f & 1;
                    mma16816(acc[mi][f], a[mi], bb[ni][ss], bb[ni][ss + 2]);
                }
            }
        }
    }
    CP_WAIT0();
    __syncthreads();

    // ---------------- epilogue ----------------
    const int rbase = wm * 64 + (lane >> 2);
    if (GELU) {
        __half* sC = (__half*)smem;          // [128][136] halfs
#pragma unroll
        for (int mi = 0; mi < 4; mi++) {
#pragma unroll
            for (int f = 0; f < 4; f++) {
                int cidx = wn * 32 + (f >> 1) * 16 + (f & 1) * 8 + (lane & 3) * 2;
                float b0v = bs[cidx], b1v = bs[cidx + 1];
                int r0 = rbase + mi * 16;
                *(__half2*)&sC[r0 * 136 + cidx] = __floats2half2_rn(
                    gelu_f(acc[mi][f][0] + b0v), gelu_f(acc[mi][f][1] + b1v));
                *(__half2*)&sC[(r0 + 8) * 136 + cidx] = __floats2half2_rn(
                    gelu_f(acc[mi][f][2] + b0v), gelu_f(acc[mi][f][3] + b1v));
            }
        }
        __syncthreads();
        for (int v = tid; v < 128 * 16; v += 256) {
            int row = v >> 4, seg = v & 15;
            *(uint4*)(Ch + (size_t)(e * ROWS_E + m0 + row) * Ntot + n0 + seg * 8) =
                *(const uint4*)&sC[row * 136 + seg * 8];
        }
    } else {
        float* sF = (float*)smem;            // [64][132] floats per pass
#pragma unroll
        for (int p = 0; p < 2; p++) {
            if (wm == p) {
#pragma unroll
                for (int mi = 0; mi < 4; mi++) {
#pragma unroll
                    for (int f = 0; f < 4; f++) {
                        int cidx = wn * 32 + (f >> 1) * 16 + (f & 1) * 8 + (lane & 3) * 2;
                        float b0v = bs[cidx], b1v = bs[cidx + 1];
                        int r0l = (lane >> 2) + mi * 16;
                        *(float2*)&sF[r0l * 132 + cidx] =
                            make_float2(acc[mi][f][0] + b0v, acc[mi][f][1] + b1v);
                        *(float2*)&sF[(r0l + 8) * 132 + cidx] =
                            make_float2(acc[mi][f][2] + b0v, acc[mi][f][3] + b1v);
                    }
                }
            }
            __syncthreads();
            // fused combine: per slot row, scatter gate*val into out[token]
            for (int v = tid; v < 64 * 32; v += 256) {
                int row = v >> 5, seg = v & 31;
                int sid = e * ROWS_E + m0 + p * 64 + row;
                int tok = g_slot_token[sid];
                if (tok >= 0) {
                    float gate = (g_tok_e[tok * 2] == e) ? g_tok_g[tok * 2]
                                                         : g_tok_g[tok * 2 + 1];
                    float* op = fout + (size_t)tok * DD + n0 + seg * 4;
                    const float* sp = &sF[row * 132 + seg * 4];
                    atomicAdd(op + 0, gate * sp[0]);
                    atomicAdd(op + 1, gate * sp[1]);
                    atomicAdd(op + 2, gate * sp[2]);
                    atomicAdd(op + 3, gate * sp[3]);
                }
            }
            __syncthreads();
        }
    }
}

// ---------------- launch ----------------
extern "C" void kernel_launch(void* const* d_in, const int* in_sizes, int n_in,
                              void* d_out, int out_size) {
    const float* x  = (const float*)d_in[0];
    const float* wr = (const float*)d_in[1];
    const float* w1 = (const float*)d_in[2];
    const float* b1 = (const float*)d_in[3];
    const float* w2 = (const float*)d_in[4];
    const float* b2 = (const float*)d_in[5];
    float* out = (float*)d_out;

    __half *xe, *w1t, *w2t, *h;
    cudaGetSymbolAddress((void**)&xe, g_xe);
    cudaGetSymbolAddress((void**)&w1t, g_w1t);
    cudaGetSymbolAddress((void**)&w2t, g_w2t);
    cudaGetSymbolAddress((void**)&h, g_h);

    cudaFuncSetAttribute(hmma_gemm_kernel<1024, true>,
                         cudaFuncAttributeMaxDynamicSharedMemorySize, SMEM_GEMM);
    cudaFuncSetAttribute(hmma_gemm_kernel<4096, false>,
                         cudaFuncAttributeMaxDynamicSharedMemorySize, SMEM_GEMM);

    // Streams/events created once on the first (uncaptured) correctness call
    // and reused; identical GPU work per call (graph-capture safe fork-join).
    static cudaStream_t s1 = nullptr;
    static cudaEvent_t evFork = nullptr, evW1 = nullptr, evZero = nullptr;
    static cudaEvent_t evW2 = nullptr, evR = nullptr, evImp = nullptr;
    if (s1 == nullptr) {
        cudaStreamCreateWithFlags(&s1, cudaStreamNonBlocking);
        cudaEventCreateWithFlags(&evFork, cudaEventDisableTiming);
        cudaEventCreateWithFlags(&evW1, cudaEventDisableTiming);
        cudaEventCreateWithFlags(&evZero, cudaEventDisableTiming);
        cudaEventCreateWithFlags(&evW2, cudaEventDisableTiming);
        cudaEventCreateWithFlags(&evR, cudaEventDisableTiming);
        cudaEventCreateWithFlags(&evImp, cudaEventDisableTiming);
    }

    // Fork: transposes + zero + imp on s1 concurrent with routing/GEMM chain.
    cudaEventRecord(evFork, 0);
    cudaStreamWaitEvent(s1, evFork, 0);

    // s1: w1 transpose, output zeroing, w2 transpose
    transpose_half_kernel<1024, 4096>
        <<<dim3(4096 / 32, 1024 / 64, EE), dim3(32, 8), 0, s1>>>(w1, w1t);
    cudaEventRecord(evW1, s1);
    zero_out_kernel<<<(NTOK * DD / 4) / 256, 256, 0, s1>>>(out);
    cudaEventRecord(evZero, s1);
    transpose_half_kernel<4096, 1024>
        <<<dim3(1024 / 32, 4096 / 64, EE), dim3(32, 8), 0, s1>>>(w2, w2t);
    cudaEventRecord(evW2, s1);

    // stream 0: routing chain
    router_kernel<<<NTOK / 8, 256>>>(x, wr);
    cudaEventRecord(evR, 0);
    scan_kernel<<<GG, 1024>>>();
    gather_kernel<<<SLOTS, 128>>>(x);

    // s1: importance reduction (depends only on router output)
    cudaStreamWaitEvent(s1, evR, 0);
    imp_kernel<<<GG, 256, 0, s1>>>();
    cudaEventRecord(evImp, s1);

    // GEMM1 needs xe (stream 0) + w1t (s1)
    cudaStreamWaitEvent(0, evW1, 0);
    hmma_gemm_kernel<1024, true>
        <<<dim3(MM / BN, ROWS_E / BM, EE), 256, SMEM_GEMM>>>(
            xe, w1t, b1, h, nullptr, MM);

    // GEMM2 (fused combine -> out) needs h, w2t, and zeroed out
    cudaStreamWaitEvent(0, evW2, 0);
    cudaStreamWaitEvent(0, evZero, 0);
    hmma_gemm_kernel<4096, false>
        <<<dim3(DD / BN, ROWS_E / BM, EE), 256, SMEM_GEMM>>>(
            h, w2t, b2, nullptr, out, DD);

    // Trailing node on stream 0 joins the s1 branch and writes the aux loss.
    cudaStreamWaitEvent(0, evImp, 0);
    if (out_size > NTOK * DD) aux_kernel<<<1, 1>>>(out);
}